// round 8
// baseline (speedup 1.0000x reference)
#include <cuda_runtime.h>

#define TPB 208        // 16 bl-groups * 13 nodes; each thread does 2 batch elems
#define NB  32         // batch elems per block
#define NGRID 1024     // 32768 / 32

#define ARENA_BYTES 6048
#define HDR_BYTES   1024
#define SMEM_TOTAL  (HDR_BYTES + NB * ARENA_BYTES)   // 194560

// ---- packed weight table offsets (float4 units) ----
#define OFF_W0    0
#define OFF_W1    256
#define OFF_DEC   512
#define OFF_FC1   768
#define OFF_FC2   832
#define OFF_B0    896
#define OFF_B1    912
#define OFF_DECB  928
#define OFF_FC1B  944
#define OFF_FC2B  948
#define OFF_WINIT 952   // 52 entries -> 1004

__constant__ float4 cw4[1008];      // read via const port (LDC/LDCU), not l1tex
__device__   float4 g_stage[1008];  // staging, written by prep_kernel

// packed f32x2 FMA (sm_100+): r = a*b + c per 32-bit half
__device__ __forceinline__ float2 ffma2(float2 a, float2 b, float2 c) {
    unsigned long long ua = *reinterpret_cast<unsigned long long*>(&a);
    unsigned long long ub = *reinterpret_cast<unsigned long long*>(&b);
    unsigned long long uc = *reinterpret_cast<unsigned long long*>(&c);
    unsigned long long ur;
    asm("fma.rn.f32x2 %0, %1, %2, %3;" : "=l"(ur) : "l"(ua), "l"(ub), "l"(uc));
    return *reinterpret_cast<float2*>(&ur);
}

__device__ __forceinline__ float2 lo2(float4 v) { return make_float2(v.x, v.y); }
__device__ __forceinline__ float2 hi2(float4 v) { return make_float2(v.z, v.w); }

__device__ __forceinline__ float getf2(const float2* v, int d) {
    return (d & 1) ? v[d >> 1].y : v[d >> 1].x;
}

__device__ __forceinline__ float lky(float v) { return fmaxf(v, 0.01f * v); }

// dual 16x16 matmul, weights from CONSTANT memory (uniform, const port)
__device__ __forceinline__ void mm16c(float2* oa, float2* ob,
                                      const float2* ia, const float2* ib,
                                      int base) {
#pragma unroll
    for (int d = 0; d < 16; d++) {
        float av = getf2(ia, d), bv = getf2(ib, d);
        float2 ap = make_float2(av, av), bp = make_float2(bv, bv);
        float4 q0 = cw4[base + d * 4 + 0];
        float4 q1 = cw4[base + d * 4 + 1];
        float4 q2 = cw4[base + d * 4 + 2];
        float4 q3 = cw4[base + d * 4 + 3];
        oa[0] = ffma2(ap, lo2(q0), oa[0]);  ob[0] = ffma2(bp, lo2(q0), ob[0]);
        oa[1] = ffma2(ap, hi2(q0), oa[1]);  ob[1] = ffma2(bp, hi2(q0), ob[1]);
        oa[2] = ffma2(ap, lo2(q1), oa[2]);  ob[2] = ffma2(bp, lo2(q1), ob[2]);
        oa[3] = ffma2(ap, hi2(q1), oa[3]);  ob[3] = ffma2(bp, hi2(q1), ob[3]);
        oa[4] = ffma2(ap, lo2(q2), oa[4]);  ob[4] = ffma2(bp, lo2(q2), ob[4]);
        oa[5] = ffma2(ap, hi2(q2), oa[5]);  ob[5] = ffma2(bp, hi2(q2), ob[5]);
        oa[6] = ffma2(ap, lo2(q3), oa[6]);  ob[6] = ffma2(bp, lo2(q3), ob[6]);
        oa[7] = ffma2(ap, hi2(q3), oa[7]);  ob[7] = ffma2(bp, hi2(q3), ob[7]);
    }
}

__device__ __forceinline__ void load8c(float2* dst, int base) {
    float4 c0 = cw4[base+0], c1 = cw4[base+1], c2 = cw4[base+2], c3 = cw4[base+3];
    dst[0] = lo2(c0); dst[1] = hi2(c0); dst[2] = lo2(c1); dst[3] = hi2(c1);
    dst[4] = lo2(c2); dst[5] = hi2(c2); dst[6] = lo2(c3); dst[7] = hi2(c3);
}

// ---- prep kernel: pack/transpose weights into staging buffer ----
__global__ void prep_kernel(
    const float* __restrict__ init_weight,
    const float* __restrict__ mlp_w0, const float* __restrict__ mlp_b0,
    const float* __restrict__ mlp_w1, const float* __restrict__ mlp_b1,
    const float* __restrict__ fc1_w, const float* __restrict__ fc1_b,
    const float* __restrict__ fc2_w, const float* __restrict__ fc2_b,
    const float* __restrict__ dec_w, const float* __restrict__ dec_b)
{
    int t = threadIdx.x;   // 256 threads
    {
        int l = t >> 6, d = (t >> 2) & 15, q = t & 3;
        const float* w  = mlp_w0 + l * 256;
        const float* w1 = mlp_w1 + l * 256;
        const float* dw = dec_w  + l * 256;
        g_stage[OFF_W0 + t]  = make_float4(w [(4*q+0)*16+d], w [(4*q+1)*16+d], w [(4*q+2)*16+d], w [(4*q+3)*16+d]);
        g_stage[OFF_W1 + t]  = make_float4(w1[(4*q+0)*16+d], w1[(4*q+1)*16+d], w1[(4*q+2)*16+d], w1[(4*q+3)*16+d]);
        g_stage[OFF_DEC + t] = make_float4(dw[(4*q+0)*16+d], dw[(4*q+1)*16+d], dw[(4*q+2)*16+d], dw[(4*q+3)*16+d]);
    }
    if (t < 64) {
        int d = t >> 2, q = t & 3;
        g_stage[OFF_FC1 + t] = make_float4(fc1_w[(4*q+0)*16+d], fc1_w[(4*q+1)*16+d], fc1_w[(4*q+2)*16+d], fc1_w[(4*q+3)*16+d]);
        g_stage[OFF_FC2 + t] = make_float4(fc2_w[(4*q+0)*16+d], fc2_w[(4*q+1)*16+d], fc2_w[(4*q+2)*16+d], fc2_w[(4*q+3)*16+d]);
    }
    if (t < 52) g_stage[OFF_WINIT + t] = ((const float4*)init_weight)[t];
    if (t < 16) {
        g_stage[OFF_B0 + t]   = ((const float4*)mlp_b0)[t];
        g_stage[OFF_B1 + t]   = ((const float4*)mlp_b1)[t];
        g_stage[OFF_DECB + t] = ((const float4*)dec_b)[t];
    }
    if (t < 4) {
        g_stage[OFF_FC1B + t] = ((const float4*)fc1_b)[t];
        g_stage[OFF_FC2B + t] = ((const float4*)fc2_b)[t];
    }
}

__global__ __launch_bounds__(TPB, 1)
void vae_kernel(
    const float* __restrict__ adj,          // (B,4,13,13)
    const float* __restrict__ eps_param,    // (4)
    const float* __restrict__ bn_in_gamma,  // (4,13)
    const float* __restrict__ bn_in_beta,
    const float* __restrict__ bn_in_mean,
    const float* __restrict__ bn_in_var,
    const float* __restrict__ bn_out_gamma,
    const float* __restrict__ bn_out_beta,
    const float* __restrict__ bn_out_mean,
    const float* __restrict__ bn_out_var,
    float* __restrict__ d_out)
{
    extern __shared__ char sm[];
    float2* bninq  = (float2*)(sm + 0);     // [4][13] (s,t)
    float2* bnoutq = (float2*)(sm + 416);   // [4][13] (s,t)
    float*  eps1   = (float*)(sm + 832);    // [4]
    char*   arenas = sm + HDR_BYTES;

    const int t = threadIdx.x;

    for (int idx = t; idx < 52; idx += TPB) {           // 4*13 BN fold
        float s = bn_in_gamma[idx] * rsqrtf(bn_in_var[idx] + 1e-5f);
        bninq[idx] = make_float2(s, bn_in_beta[idx] - bn_in_mean[idx] * s);
        float so = bn_out_gamma[idx] * rsqrtf(bn_out_var[idx] + 1e-5f);
        bnoutq[idx] = make_float2(so, bn_out_beta[idx] - bn_out_mean[idx] * so);
    }
    if (t < 4) eps1[t] = 1.0f + eps_param[t];

    // ---- load adj (coalesced float4) into per-b arenas ----
    const float4* adjg = (const float4*)(adj + (size_t)blockIdx.x * NB * 676);
    for (int i = t; i < NB * 169; i += TPB) {           // 26 iters exactly
        int b = i / 169, q = i - b * 169;
        *(float4*)(arenas + b * ARENA_BYTES + q * 16) = adjg[i];
    }
    __syncthreads();

    // ---- per-thread: (bl, n) handles arenas bl and bl+16 ----
    const int bl = t / 13;
    const int n  = t - bl * 13;
    char* arA = arenas + bl * ARENA_BYTES;
    char* arB = arenas + (bl + 16) * ARENA_BYTES;
    float*  adjA = (float*)arA;                  // [g*169 + n*13 + m]
    float*  adjB = (float*)arB;
    float4* xA0  = (float4*)(arA + 2704);        // [13][4]
    float4* xA1  = (float4*)(arA + 3536);
    float4* xB0  = (float4*)(arB + 2704);
    float4* xB1  = (float4*)(arB + 3536);

    // ---- x init ----
    float2 xa[8], xb[8];
#pragma unroll
    for (int j = 0; j < 8; j++) { xa[j] = make_float2(0.f, 0.f); xb[j] = make_float2(0.f, 0.f); }
#pragma unroll
    for (int m = 0; m < 13; m++) {
        int o = n * 13 + m;
        float sa = adjA[o] + adjA[169 + o] + adjA[338 + o] + adjA[507 + o];
        float sb = adjB[o] + adjB[169 + o] + adjB[338 + o] + adjB[507 + o];
        float2 ap = make_float2(sa, sa), bp = make_float2(sb, sb);
        float4 q0 = cw4[OFF_WINIT + m*4+0];
        float4 q1 = cw4[OFF_WINIT + m*4+1];
        float4 q2 = cw4[OFF_WINIT + m*4+2];
        float4 q3 = cw4[OFF_WINIT + m*4+3];
        xa[0] = ffma2(ap, lo2(q0), xa[0]);  xb[0] = ffma2(bp, lo2(q0), xb[0]);
        xa[1] = ffma2(ap, hi2(q0), xa[1]);  xb[1] = ffma2(bp, hi2(q0), xb[1]);
        xa[2] = ffma2(ap, lo2(q1), xa[2]);  xb[2] = ffma2(bp, lo2(q1), xb[2]);
        xa[3] = ffma2(ap, hi2(q1), xa[3]);  xb[3] = ffma2(bp, hi2(q1), xb[3]);
        xa[4] = ffma2(ap, lo2(q2), xa[4]);  xb[4] = ffma2(bp, lo2(q2), xb[4]);
        xa[5] = ffma2(ap, hi2(q2), xa[5]);  xb[5] = ffma2(bp, hi2(q2), xb[5]);
        xa[6] = ffma2(ap, lo2(q3), xa[6]);  xb[6] = ffma2(bp, lo2(q3), xb[6]);
        xa[7] = ffma2(ap, hi2(q3), xa[7]);  xb[7] = ffma2(bp, hi2(q3), xb[7]);
    }
#pragma unroll
    for (int q = 0; q < 4; q++) {
        xA0[n*4+q] = make_float4(xa[2*q].x, xa[2*q].y, xa[2*q+1].x, xa[2*q+1].y);
        xB0[n*4+q] = make_float4(xb[2*q].x, xb[2*q].y, xb[2*q+1].x, xb[2*q+1].y);
    }
    __syncthreads();

    // ---- 4 GIN layers ----
#pragma unroll
    for (int l = 0; l < 4; l++) {
        const float4* xrdA = (l & 1) ? xA1 : xA0;
        const float4* xrdB = (l & 1) ? xB1 : xB0;
        float4*       xwrA = (l & 1) ? xA0 : xA1;
        float4*       xwrB = (l & 1) ? xB0 : xB1;

        float2 na[8], nb[8];
#pragma unroll
        for (int j = 0; j < 8; j++) { na[j] = make_float2(0.f, 0.f); nb[j] = make_float2(0.f, 0.f); }
#pragma unroll
        for (int m = 0; m < 13; m++) {
            int o = n * 13 + m;
            {
                float a0 = adjA[o], a1 = adjA[169+o], a2 = adjA[338+o], a3 = adjA[507+o];
                float2 g0 = make_float2(a0,a0), g1 = make_float2(a1,a1);
                float2 g2 = make_float2(a2,a2), g3 = make_float2(a3,a3);
                float4 m0 = xrdA[m*4+0], m1 = xrdA[m*4+1], m2 = xrdA[m*4+2], m3 = xrdA[m*4+3];
                na[0] = ffma2(g0, lo2(m0), na[0]);  na[1] = ffma2(g0, hi2(m0), na[1]);
                na[2] = ffma2(g1, lo2(m1), na[2]);  na[3] = ffma2(g1, hi2(m1), na[3]);
                na[4] = ffma2(g2, lo2(m2), na[4]);  na[5] = ffma2(g2, hi2(m2), na[5]);
                na[6] = ffma2(g3, lo2(m3), na[6]);  na[7] = ffma2(g3, hi2(m3), na[7]);
            }
            {
                float a0 = adjB[o], a1 = adjB[169+o], a2 = adjB[338+o], a3 = adjB[507+o];
                float2 g0 = make_float2(a0,a0), g1 = make_float2(a1,a1);
                float2 g2 = make_float2(a2,a2), g3 = make_float2(a3,a3);
                float4 m0 = xrdB[m*4+0], m1 = xrdB[m*4+1], m2 = xrdB[m*4+2], m3 = xrdB[m*4+3];
                nb[0] = ffma2(g0, lo2(m0), nb[0]);  nb[1] = ffma2(g0, hi2(m0), nb[1]);
                nb[2] = ffma2(g1, lo2(m1), nb[2]);  nb[3] = ffma2(g1, hi2(m1), nb[3]);
                nb[4] = ffma2(g2, lo2(m2), nb[4]);  nb[5] = ffma2(g2, hi2(m2), nb[5]);
                nb[6] = ffma2(g3, lo2(m3), nb[6]);  nb[7] = ffma2(g3, hi2(m3), nb[7]);
            }
        }
        float e = eps1[l];
        float2 ep = make_float2(e, e);
        float2 aga[8], agb[8];
#pragma unroll
        for (int j = 0; j < 8; j++) {
            aga[j] = ffma2(ep, xa[j], na[j]);
            agb[j] = ffma2(ep, xb[j], nb[j]);
        }

        // h1 = agg @ w0^T + b0 -> BN_in -> leaky
        float2 ha[8], hb[8];
        load8c(ha, OFF_B0 + l*4); load8c(hb, OFF_B0 + l*4);
        mm16c(ha, hb, aga, agb, OFF_W0 + l * 64);
        {
            float2 st = bninq[l * 13 + n];
            float2 sp = make_float2(st.x, st.x), tp = make_float2(st.y, st.y);
#pragma unroll
            for (int j = 0; j < 8; j++) {
                ha[j] = ffma2(sp, ha[j], tp);
                ha[j].x = lky(ha[j].x); ha[j].y = lky(ha[j].y);
                hb[j] = ffma2(sp, hb[j], tp);
                hb[j].x = lky(hb[j].x); hb[j].y = lky(hb[j].y);
            }
        }
        // out = h1 @ w1^T + b1 -> BN_out -> leaky -> new x
        float2 oa[8], ob[8];
        load8c(oa, OFF_B1 + l*4); load8c(ob, OFF_B1 + l*4);
        mm16c(oa, ob, ha, hb, OFF_W1 + l * 64);
        {
            float2 st = bnoutq[l * 13 + n];
            float2 sp = make_float2(st.x, st.x), tp = make_float2(st.y, st.y);
#pragma unroll
            for (int j = 0; j < 8; j++) {
                oa[j] = ffma2(sp, oa[j], tp);
                oa[j].x = lky(oa[j].x); oa[j].y = lky(oa[j].y);
                xa[j] = oa[j];
                ob[j] = ffma2(sp, ob[j], tp);
                ob[j].x = lky(ob[j].x); ob[j].y = lky(ob[j].y);
                xb[j] = ob[j];
            }
        }
        if (l < 3) {
#pragma unroll
            for (int q = 0; q < 4; q++) {
                xwrA[n*4+q] = make_float4(xa[2*q].x, xa[2*q].y, xa[2*q+1].x, xa[2*q+1].y);
                xwrB[n*4+q] = make_float4(xb[2*q].x, xb[2*q].y, xb[2*q+1].x, xb[2*q+1].y);
            }
            __syncthreads();
        }
    }

    // ---- fc heads: mu, logvar ----
    float2 mua[8], mub[8], lva[8], lvb[8];
    load8c(mua, OFF_FC1B); load8c(mub, OFF_FC1B);
    load8c(lva, OFF_FC2B); load8c(lvb, OFF_FC2B);
    mm16c(mua, mub, xa, xb, OFF_FC1);
    mm16c(lva, lvb, xa, xb, OFF_FC2);
    {
        size_t bgA = (size_t)blockIdx.x * NB + bl;
        size_t bgB = bgA + 16;
        float* muoA = d_out + 22151168ull + (bgA * 13 + n) * 16;
        float* lvoA = d_out + 28966912ull + (bgA * 13 + n) * 16;
        float* muoB = d_out + 22151168ull + (bgB * 13 + n) * 16;
        float* lvoB = d_out + 28966912ull + (bgB * 13 + n) * 16;
#pragma unroll
        for (int q = 0; q < 4; q++) {
            ((float4*)muoA)[q] = make_float4(mua[2*q].x, mua[2*q].y, mua[2*q+1].x, mua[2*q+1].y);
            ((float4*)lvoA)[q] = make_float4(lva[2*q].x, lva[2*q].y, lva[2*q+1].x, lva[2*q+1].y);
            ((float4*)muoB)[q] = make_float4(mub[2*q].x, mub[2*q].y, mub[2*q+1].x, mub[2*q+1].y);
            ((float4*)lvoB)[q] = make_float4(lvb[2*q].x, lvb[2*q].y, lvb[2*q+1].x, lvb[2*q+1].y);
        }
    }

    // Fence: layer-3 adj + x-row reads complete before tS overlay
    __syncthreads();

    // ---- decoder: temp[k][n][d] = mu @ dec_w[k]^T + dec_b[k] ----
    float4* tSA = (float4*)arA;   // [k*52 + m*4 + q], overlays adj/xb0
    float4* tSB = (float4*)arB;
#pragma unroll
    for (int k = 0; k < 4; k++) {
        float2 aa[8], ab[8];
        load8c(aa, OFF_DECB + k*4); load8c(ab, OFF_DECB + k*4);
        mm16c(aa, ab, mua, mub, OFF_DEC + k * 64);
#pragma unroll
        for (int q = 0; q < 4; q++) {
            tSA[k*52 + n*4 + q] = make_float4(aa[2*q].x, aa[2*q].y, aa[2*q+1].x, aa[2*q+1].y);
            tSB[k*52 + n*4 + q] = make_float4(ab[2*q].x, ab[2*q].y, ab[2*q+1].x, ab[2*q+1].y);
        }
    }
    __syncthreads();

    // ---- recon: symmetric gram, compute m<=n, mirror ----
#pragma unroll
    for (int e = 0; e < 2; e++) {
        const float4* tS = e ? tSB : tSA;
        float* reconS = (float*)((e ? arB : arA) + 3328);  // [k*169 + n*13 + m]
#pragma unroll
        for (int k = 0; k < 4; k++) {
            float2 tn[8];
            {
                float4 q0 = tS[k*52+n*4+0], q1 = tS[k*52+n*4+1], q2 = tS[k*52+n*4+2], q3 = tS[k*52+n*4+3];
                tn[0] = lo2(q0); tn[1] = hi2(q0); tn[2] = lo2(q1); tn[3] = hi2(q1);
                tn[4] = lo2(q2); tn[5] = hi2(q2); tn[6] = lo2(q3); tn[7] = hi2(q3);
            }
            for (int m = 0; m <= n; m++) {
                float4 q0 = tS[k*52+m*4+0], q1 = tS[k*52+m*4+1], q2 = tS[k*52+m*4+2], q3 = tS[k*52+m*4+3];
                float2 acc = make_float2(0.f, 0.f);
                acc = ffma2(tn[0], lo2(q0), acc);  acc = ffma2(tn[1], hi2(q0), acc);
                acc = ffma2(tn[2], lo2(q1), acc);  acc = ffma2(tn[3], hi2(q1), acc);
                acc = ffma2(tn[4], lo2(q2), acc);  acc = ffma2(tn[5], hi2(q2), acc);
                acc = ffma2(tn[6], lo2(q3), acc);  acc = ffma2(tn[7], hi2(q3), acc);
                float v = fmaxf(acc.x + acc.y, 0.0f);
                reconS[k * 169 + n * 13 + m] = v;
                if (m < n) reconS[k * 169 + m * 13 + n] = v;
            }
        }
    }
    __syncthreads();

    // ---- coalesced recon flush (float4) ----
    {
        float4* outg = (float4*)d_out;
        size_t base4 = (size_t)blockIdx.x * NB * 169;
        for (int i = t; i < NB * 169; i += TPB) {       // 26 iters exactly
            int b = i / 169, q = i - b * 169;
            outg[base4 + i] = *(const float4*)(arenas + b * ARENA_BYTES + 3328 + q * 16);
        }
    }
}

extern "C" void kernel_launch(void* const* d_in, const int* in_sizes, int n_in,
                              void* d_out, int out_size) {
    (void)in_sizes; (void)n_in; (void)out_size;
    prep_kernel<<<1, 256>>>(
        (const float*)d_in[1],
        (const float*)d_in[3],  (const float*)d_in[4],
        (const float*)d_in[5],  (const float*)d_in[6],
        (const float*)d_in[15], (const float*)d_in[16],
        (const float*)d_in[17], (const float*)d_in[18],
        (const float*)d_in[19], (const float*)d_in[20]);
    void* dst_ptr = 0;
    void* src_ptr = 0;
    cudaGetSymbolAddress(&dst_ptr, cw4);
    cudaGetSymbolAddress(&src_ptr, g_stage);
    cudaMemcpyAsync(dst_ptr, src_ptr, 1008 * sizeof(float4),
                    cudaMemcpyDeviceToDevice, 0);
    cudaFuncSetAttribute(vae_kernel, cudaFuncAttributeMaxDynamicSharedMemorySize, SMEM_TOTAL);
    vae_kernel<<<NGRID, TPB, SMEM_TOTAL>>>(
        (const float*)d_in[0],  (const float*)d_in[2],
        (const float*)d_in[7],  (const float*)d_in[8],
        (const float*)d_in[9],  (const float*)d_in[10],
        (const float*)d_in[11], (const float*)d_in[12],
        (const float*)d_in[13], (const float*)d_in[14],
        (float*)d_out);
}

// round 9
// speedup vs baseline: 1.8500x; 1.8500x over previous
#include <cuda_runtime.h>

#define TPB 104        // 8 bl-groups * 13 nodes; each thread does 2 batch elems
#define NB  16         // batch elems per block
#define NGRID 2048     // 32768 / 16

#define ARENA_BYTES 3536
#define WREG_BYTES  16912
#define SMEM_TOTAL  (WREG_BYTES + NB * ARENA_BYTES)   // 73488 -> 3 CTAs/SM

// packed f32x2 FMA (sm_100+): r = a*b + c per 32-bit half
__device__ __forceinline__ float2 ffma2(float2 a, float2 b, float2 c) {
    unsigned long long ua = *reinterpret_cast<unsigned long long*>(&a);
    unsigned long long ub = *reinterpret_cast<unsigned long long*>(&b);
    unsigned long long uc = *reinterpret_cast<unsigned long long*>(&c);
    unsigned long long ur;
    asm("fma.rn.f32x2 %0, %1, %2, %3;" : "=l"(ur) : "l"(ua), "l"(ub), "l"(uc));
    return *reinterpret_cast<float2*>(&ur);
}

__device__ __forceinline__ float2 lo2(float4 v) { return make_float2(v.x, v.y); }
__device__ __forceinline__ float2 hi2(float4 v) { return make_float2(v.z, v.w); }

__device__ __forceinline__ float getf2(const float2* v, int d) {
    return (d & 1) ? v[d >> 1].y : v[d >> 1].x;
}

__device__ __forceinline__ float lky(float v) { return fmaxf(v, 0.01f * v); }

// dual 16x16 matmul: one weight read feeds BOTH accumulator streams
__device__ __forceinline__ void mm16d(float2* oa, float2* ob,
                                      const float2* ia, const float2* ib,
                                      const float4* Wq) {
#pragma unroll
    for (int d = 0; d < 16; d++) {
        float av = getf2(ia, d), bv = getf2(ib, d);
        float2 ap = make_float2(av, av), bp = make_float2(bv, bv);
        float4 q0 = Wq[d * 4 + 0];
        float4 q1 = Wq[d * 4 + 1];
        float4 q2 = Wq[d * 4 + 2];
        float4 q3 = Wq[d * 4 + 3];
        oa[0] = ffma2(ap, lo2(q0), oa[0]);  ob[0] = ffma2(bp, lo2(q0), ob[0]);
        oa[1] = ffma2(ap, hi2(q0), oa[1]);  ob[1] = ffma2(bp, hi2(q0), ob[1]);
        oa[2] = ffma2(ap, lo2(q1), oa[2]);  ob[2] = ffma2(bp, lo2(q1), ob[2]);
        oa[3] = ffma2(ap, hi2(q1), oa[3]);  ob[3] = ffma2(bp, hi2(q1), ob[3]);
        oa[4] = ffma2(ap, lo2(q2), oa[4]);  ob[4] = ffma2(bp, lo2(q2), ob[4]);
        oa[5] = ffma2(ap, hi2(q2), oa[5]);  ob[5] = ffma2(bp, hi2(q2), ob[5]);
        oa[6] = ffma2(ap, lo2(q3), oa[6]);  ob[6] = ffma2(bp, lo2(q3), ob[6]);
        oa[7] = ffma2(ap, hi2(q3), oa[7]);  ob[7] = ffma2(bp, hi2(q3), ob[7]);
    }
}

__device__ __forceinline__ void load8s(float2* dst, const float4* src) {
    float4 c0 = src[0], c1 = src[1], c2 = src[2], c3 = src[3];
    dst[0] = lo2(c0); dst[1] = hi2(c0); dst[2] = lo2(c1); dst[3] = hi2(c1);
    dst[4] = lo2(c2); dst[5] = hi2(c2); dst[6] = lo2(c3); dst[7] = hi2(c3);
}

__global__ __launch_bounds__(TPB, 3)
void vae_kernel(
    const float* __restrict__ adj,          // (B,4,13,13)
    const float* __restrict__ init_weight,  // (13,16)
    const float* __restrict__ eps_param,    // (4)
    const float* __restrict__ mlp_w0,       // (4,16,16)
    const float* __restrict__ mlp_b0,       // (4,16)
    const float* __restrict__ mlp_w1,       // (4,16,16)
    const float* __restrict__ mlp_b1,       // (4,16)
    const float* __restrict__ bn_in_gamma,  // (4,13)
    const float* __restrict__ bn_in_beta,
    const float* __restrict__ bn_in_mean,
    const float* __restrict__ bn_in_var,
    const float* __restrict__ bn_out_gamma,
    const float* __restrict__ bn_out_beta,
    const float* __restrict__ bn_out_mean,
    const float* __restrict__ bn_out_var,
    const float* __restrict__ fc1_w,        // (16,16)
    const float* __restrict__ fc1_b,        // (16)
    const float* __restrict__ fc2_w,
    const float* __restrict__ fc2_b,
    const float* __restrict__ dec_w,        // (4,16,16)
    const float* __restrict__ dec_b,        // (4,16)
    float* __restrict__ d_out)
{
    extern __shared__ char sm[];
    float4* w0q   = (float4*)(sm + 0);      // [4][16][4]
    float4* w1q   = (float4*)(sm + 4096);   // [4][16][4]
    float4* decq  = (float4*)(sm + 8192);   // [4][16][4]
    float4* fc1q  = (float4*)(sm + 12288);  // [16][4]
    float4* fc2q  = (float4*)(sm + 13312);  // [16][4]
    float4* b0q   = (float4*)(sm + 14336);  // [4][4]
    float4* b1q   = (float4*)(sm + 14592);  // [4][4]
    float4* decbq = (float4*)(sm + 14848);  // [4][4]
    float4* fc1bq = (float4*)(sm + 15104);  // [4]
    float4* fc2bq = (float4*)(sm + 15168);  // [4]
    float2* bninq = (float2*)(sm + 15232);  // [4][13] (s,t)
    float2* bnoutq= (float2*)(sm + 15648);  // [4][13] (s,t)
    float4* winitq= (float4*)(sm + 16064);  // [13][4]
    float*  eps1  = (float*)(sm + 16896);   // [4]
    char*   arenas = sm + WREG_BYTES;

    const int t = threadIdx.x;

    // ---- stage transposed/packed weights ----
    for (int idx = t; idx < 256; idx += TPB) {          // 4*16*4
        int l = idx >> 6, d = (idx >> 2) & 15, q = idx & 3;
        const float* w  = mlp_w0 + l * 256;
        const float* w1 = mlp_w1 + l * 256;
        const float* dw = dec_w  + l * 256;
        w0q[idx]  = make_float4(w [(4*q+0)*16+d], w [(4*q+1)*16+d], w [(4*q+2)*16+d], w [(4*q+3)*16+d]);
        w1q[idx]  = make_float4(w1[(4*q+0)*16+d], w1[(4*q+1)*16+d], w1[(4*q+2)*16+d], w1[(4*q+3)*16+d]);
        decq[idx] = make_float4(dw[(4*q+0)*16+d], dw[(4*q+1)*16+d], dw[(4*q+2)*16+d], dw[(4*q+3)*16+d]);
    }
    for (int idx = t; idx < 64; idx += TPB) {           // 16*4
        int d = idx >> 2, q = idx & 3;
        fc1q[idx] = make_float4(fc1_w[(4*q+0)*16+d], fc1_w[(4*q+1)*16+d], fc1_w[(4*q+2)*16+d], fc1_w[(4*q+3)*16+d]);
        fc2q[idx] = make_float4(fc2_w[(4*q+0)*16+d], fc2_w[(4*q+1)*16+d], fc2_w[(4*q+2)*16+d], fc2_w[(4*q+3)*16+d]);
    }
    for (int idx = t; idx < 52; idx += TPB)             // 13*4
        winitq[idx] = ((const float4*)init_weight)[idx];
    for (int idx = t; idx < 16; idx += TPB) {           // 4*4
        b0q[idx]   = ((const float4*)mlp_b0)[idx];
        b1q[idx]   = ((const float4*)mlp_b1)[idx];
        decbq[idx] = ((const float4*)dec_b)[idx];
    }
    if (t < 4) {
        fc1bq[t] = ((const float4*)fc1_b)[t];
        fc2bq[t] = ((const float4*)fc2_b)[t];
        eps1[t]  = 1.0f + eps_param[t];
    }
    for (int idx = t; idx < 52; idx += TPB) {           // 4*13 BN fold
        float s = bn_in_gamma[idx] * rsqrtf(bn_in_var[idx] + 1e-5f);
        bninq[idx] = make_float2(s, bn_in_beta[idx] - bn_in_mean[idx] * s);
        float so = bn_out_gamma[idx] * rsqrtf(bn_out_var[idx] + 1e-5f);
        bnoutq[idx] = make_float2(so, bn_out_beta[idx] - bn_out_mean[idx] * so);
    }

    // ---- load adj (coalesced float4) into per-b arenas ----
    const float4* adjg = (const float4*)(adj + (size_t)blockIdx.x * NB * 676);
    for (int i = t; i < NB * 169; i += TPB) {           // 26 iters exactly
        int b = i / 169, q = i - b * 169;
        *(float4*)(arenas + b * ARENA_BYTES + q * 16) = adjg[i];
    }
    __syncthreads();

    // ---- per-thread: (bl, n) handles arenas bl and bl+8 ----
    const int bl = t / 13;
    const int n  = t - bl * 13;
    char* arA = arenas + bl * ARENA_BYTES;
    char* arB = arenas + (bl + 8) * ARENA_BYTES;
    float*  adjA = (float*)arA;                  // [g*169 + n*13 + m]
    float*  adjB = (float*)arB;
    float4* xA   = (float4*)(arA + 2704);        // [13][4] single buffer
    float4* xB   = (float4*)(arB + 2704);

    // ---- x init ----
    float2 xa[8], xb[8];
#pragma unroll
    for (int j = 0; j < 8; j++) { xa[j] = make_float2(0.f, 0.f); xb[j] = make_float2(0.f, 0.f); }
#pragma unroll
    for (int m = 0; m < 13; m++) {
        int o = n * 13 + m;
        float sa = adjA[o] + adjA[169 + o] + adjA[338 + o] + adjA[507 + o];
        float sb = adjB[o] + adjB[169 + o] + adjB[338 + o] + adjB[507 + o];
        float2 ap = make_float2(sa, sa), bp = make_float2(sb, sb);
        float4 q0 = winitq[m*4+0], q1 = winitq[m*4+1], q2 = winitq[m*4+2], q3 = winitq[m*4+3];
        xa[0] = ffma2(ap, lo2(q0), xa[0]);  xb[0] = ffma2(bp, lo2(q0), xb[0]);
        xa[1] = ffma2(ap, hi2(q0), xa[1]);  xb[1] = ffma2(bp, hi2(q0), xb[1]);
        xa[2] = ffma2(ap, lo2(q1), xa[2]);  xb[2] = ffma2(bp, lo2(q1), xb[2]);
        xa[3] = ffma2(ap, hi2(q1), xa[3]);  xb[3] = ffma2(bp, hi2(q1), xb[3]);
        xa[4] = ffma2(ap, lo2(q2), xa[4]);  xb[4] = ffma2(bp, lo2(q2), xb[4]);
        xa[5] = ffma2(ap, hi2(q2), xa[5]);  xb[5] = ffma2(bp, hi2(q2), xb[5]);
        xa[6] = ffma2(ap, lo2(q3), xa[6]);  xb[6] = ffma2(bp, lo2(q3), xb[6]);
        xa[7] = ffma2(ap, hi2(q3), xa[7]);  xb[7] = ffma2(bp, hi2(q3), xb[7]);
    }
#pragma unroll
    for (int q = 0; q < 4; q++) {
        xA[n*4+q] = make_float4(xa[2*q].x, xa[2*q].y, xa[2*q+1].x, xa[2*q+1].y);
        xB[n*4+q] = make_float4(xb[2*q].x, xb[2*q].y, xb[2*q+1].x, xb[2*q+1].y);
    }
    __syncthreads();

    // ---- 4 GIN layers (single x buffer: sync after reads, sync after write) ----
#pragma unroll
    for (int l = 0; l < 4; l++) {
        float2 na[8], nb[8];
#pragma unroll
        for (int j = 0; j < 8; j++) { na[j] = make_float2(0.f, 0.f); nb[j] = make_float2(0.f, 0.f); }
#pragma unroll
        for (int m = 0; m < 13; m++) {
            int o = n * 13 + m;
            {
                float a0 = adjA[o], a1 = adjA[169+o], a2 = adjA[338+o], a3 = adjA[507+o];
                float2 g0 = make_float2(a0,a0), g1 = make_float2(a1,a1);
                float2 g2 = make_float2(a2,a2), g3 = make_float2(a3,a3);
                float4 m0 = xA[m*4+0], m1 = xA[m*4+1], m2 = xA[m*4+2], m3 = xA[m*4+3];
                na[0] = ffma2(g0, lo2(m0), na[0]);  na[1] = ffma2(g0, hi2(m0), na[1]);
                na[2] = ffma2(g1, lo2(m1), na[2]);  na[3] = ffma2(g1, hi2(m1), na[3]);
                na[4] = ffma2(g2, lo2(m2), na[4]);  na[5] = ffma2(g2, hi2(m2), na[5]);
                na[6] = ffma2(g3, lo2(m3), na[6]);  na[7] = ffma2(g3, hi2(m3), na[7]);
            }
            {
                float a0 = adjB[o], a1 = adjB[169+o], a2 = adjB[338+o], a3 = adjB[507+o];
                float2 g0 = make_float2(a0,a0), g1 = make_float2(a1,a1);
                float2 g2 = make_float2(a2,a2), g3 = make_float2(a3,a3);
                float4 m0 = xB[m*4+0], m1 = xB[m*4+1], m2 = xB[m*4+2], m3 = xB[m*4+3];
                nb[0] = ffma2(g0, lo2(m0), nb[0]);  nb[1] = ffma2(g0, hi2(m0), nb[1]);
                nb[2] = ffma2(g1, lo2(m1), nb[2]);  nb[3] = ffma2(g1, hi2(m1), nb[3]);
                nb[4] = ffma2(g2, lo2(m2), nb[4]);  nb[5] = ffma2(g2, hi2(m2), nb[5]);
                nb[6] = ffma2(g3, lo2(m3), nb[6]);  nb[7] = ffma2(g3, hi2(m3), nb[7]);
            }
        }
        if (l < 3) __syncthreads();   // all x reads done before rewrite below
        float e = eps1[l];
        float2 ep = make_float2(e, e);
        float2 aga[8], agb[8];
#pragma unroll
        for (int j = 0; j < 8; j++) {
            aga[j] = ffma2(ep, xa[j], na[j]);
            agb[j] = ffma2(ep, xb[j], nb[j]);
        }

        // h1 = agg @ w0^T + b0 -> BN_in -> leaky
        float2 ha[8], hb[8];
        load8s(ha, &b0q[l*4]); load8s(hb, &b0q[l*4]);
        mm16d(ha, hb, aga, agb, &w0q[l * 64]);
        {
            float2 st = bninq[l * 13 + n];
            float2 sp = make_float2(st.x, st.x), tp = make_float2(st.y, st.y);
#pragma unroll
            for (int j = 0; j < 8; j++) {
                ha[j] = ffma2(sp, ha[j], tp);
                ha[j].x = lky(ha[j].x); ha[j].y = lky(ha[j].y);
                hb[j] = ffma2(sp, hb[j], tp);
                hb[j].x = lky(hb[j].x); hb[j].y = lky(hb[j].y);
            }
        }
        // out = h1 @ w1^T + b1 -> BN_out -> leaky -> new x
        float2 oa[8], ob[8];
        load8s(oa, &b1q[l*4]); load8s(ob, &b1q[l*4]);
        mm16d(oa, ob, ha, hb, &w1q[l * 64]);
        {
            float2 st = bnoutq[l * 13 + n];
            float2 sp = make_float2(st.x, st.x), tp = make_float2(st.y, st.y);
#pragma unroll
            for (int j = 0; j < 8; j++) {
                oa[j] = ffma2(sp, oa[j], tp);
                oa[j].x = lky(oa[j].x); oa[j].y = lky(oa[j].y);
                xa[j] = oa[j];
                ob[j] = ffma2(sp, ob[j], tp);
                ob[j].x = lky(ob[j].x); ob[j].y = lky(ob[j].y);
                xb[j] = ob[j];
            }
        }
        if (l < 3) {
#pragma unroll
            for (int q = 0; q < 4; q++) {
                xA[n*4+q] = make_float4(xa[2*q].x, xa[2*q].y, xa[2*q+1].x, xa[2*q+1].y);
                xB[n*4+q] = make_float4(xb[2*q].x, xb[2*q].y, xb[2*q+1].x, xb[2*q+1].y);
            }
            __syncthreads();
        }
    }

    // ---- fc heads: mu, logvar ----
    float2 mua[8], mub[8], lva[8], lvb[8];
    load8s(mua, fc1bq); load8s(mub, fc1bq);
    load8s(lva, fc2bq); load8s(lvb, fc2bq);
    mm16d(mua, mub, xa, xb, fc1q);
    mm16d(lva, lvb, xa, xb, fc2q);
    {
        size_t bgA = (size_t)blockIdx.x * NB + bl;
        size_t bgB = bgA + 8;
        float* muoA = d_out + 22151168ull + (bgA * 13 + n) * 16;
        float* lvoA = d_out + 28966912ull + (bgA * 13 + n) * 16;
        float* muoB = d_out + 22151168ull + (bgB * 13 + n) * 16;
        float* lvoB = d_out + 28966912ull + (bgB * 13 + n) * 16;
#pragma unroll
        for (int q = 0; q < 4; q++) {
            ((float4*)muoA)[q] = make_float4(mua[2*q].x, mua[2*q].y, mua[2*q+1].x, mua[2*q+1].y);
            ((float4*)lvoA)[q] = make_float4(lva[2*q].x, lva[2*q].y, lva[2*q+1].x, lva[2*q+1].y);
            ((float4*)muoB)[q] = make_float4(mub[2*q].x, mub[2*q].y, mub[2*q+1].x, mub[2*q+1].y);
            ((float4*)lvoB)[q] = make_float4(lvb[2*q].x, lvb[2*q].y, lvb[2*q+1].x, lvb[2*q+1].y);
        }
    }

    // Fence: layer-3 adj + x reads complete before t/recon overlay
    __syncthreads();

    // ---- decoder + gram, per-k to fit small arena ----
    // t_k: [0,832) overlays adj; reconS: [832,3536) overlays adj tail + x
    float4* tA = (float4*)arA;
    float4* tB = (float4*)arB;
    float* rA = (float*)(arA + 832);   // [k*169 + n*13 + m]
    float* rB = (float*)(arB + 832);
#pragma unroll
    for (int k = 0; k < 4; k++) {
        if (k) __syncthreads();        // prior k's gram reads of t done
        float2 aa[8], ab[8];
        load8s(aa, &decbq[k*4]); load8s(ab, &decbq[k*4]);
        mm16d(aa, ab, mua, mub, &decq[k * 64]);
#pragma unroll
        for (int q = 0; q < 4; q++) {
            tA[n*4 + q] = make_float4(aa[2*q].x, aa[2*q].y, aa[2*q+1].x, aa[2*q+1].y);
            tB[n*4 + q] = make_float4(ab[2*q].x, ab[2*q].y, ab[2*q+1].x, ab[2*q+1].y);
        }
        __syncthreads();
        // symmetric gram: compute m<=n, mirror
#pragma unroll
        for (int e = 0; e < 2; e++) {
            const float4* tS = e ? tB : tA;
            float* rS = e ? rB : rA;
            float2 tn[8];
            {
                float4 q0 = tS[n*4+0], q1 = tS[n*4+1], q2 = tS[n*4+2], q3 = tS[n*4+3];
                tn[0] = lo2(q0); tn[1] = hi2(q0); tn[2] = lo2(q1); tn[3] = hi2(q1);
                tn[4] = lo2(q2); tn[5] = hi2(q2); tn[6] = lo2(q3); tn[7] = hi2(q3);
            }
            for (int m = 0; m <= n; m++) {
                float4 q0 = tS[m*4+0], q1 = tS[m*4+1], q2 = tS[m*4+2], q3 = tS[m*4+3];
                float2 acc = make_float2(0.f, 0.f);
                acc = ffma2(tn[0], lo2(q0), acc);  acc = ffma2(tn[1], hi2(q0), acc);
                acc = ffma2(tn[2], lo2(q1), acc);  acc = ffma2(tn[3], hi2(q1), acc);
                acc = ffma2(tn[4], lo2(q2), acc);  acc = ffma2(tn[5], hi2(q2), acc);
                acc = ffma2(tn[6], lo2(q3), acc);  acc = ffma2(tn[7], hi2(q3), acc);
                float v = fmaxf(acc.x + acc.y, 0.0f);
                rS[k * 169 + n * 13 + m] = v;
                if (m < n) rS[k * 169 + m * 13 + n] = v;
            }
        }
    }
    __syncthreads();

    // ---- coalesced recon flush (float4) ----
    {
        float4* outg = (float4*)d_out;
        size_t base4 = (size_t)blockIdx.x * NB * 169;
        for (int i = t; i < NB * 169; i += TPB) {       // 26 iters exactly
            int b = i / 169, q = i - b * 169;
            outg[base4 + i] = *(const float4*)(arenas + b * ARENA_BYTES + 832 + q * 16);
        }
    }
}

extern "C" void kernel_launch(void* const* d_in, const int* in_sizes, int n_in,
                              void* d_out, int out_size) {
    (void)in_sizes; (void)n_in; (void)out_size;
    cudaFuncSetAttribute(vae_kernel, cudaFuncAttributeMaxDynamicSharedMemorySize, SMEM_TOTAL);
    vae_kernel<<<NGRID, TPB, SMEM_TOTAL>>>(
        (const float*)d_in[0],  (const float*)d_in[1],  (const float*)d_in[2],
        (const float*)d_in[3],  (const float*)d_in[4],  (const float*)d_in[5],
        (const float*)d_in[6],  (const float*)d_in[7],  (const float*)d_in[8],
        (const float*)d_in[9],  (const float*)d_in[10], (const float*)d_in[11],
        (const float*)d_in[12], (const float*)d_in[13], (const float*)d_in[14],
        (const float*)d_in[15], (const float*)d_in[16], (const float*)d_in[17],
        (const float*)d_in[18], (const float*)d_in[19], (const float*)d_in[20],
        (float*)d_out);
}